// round 1
// baseline (speedup 1.0000x reference)
#include <cuda_runtime.h>
#include <cuda_bf16.h>

// HungarianMatcher cost computation, block-diagonal only.
// Shapes: BS=16, Q=1000, NC=80, T=100, NI=8
// Inputs (metadata order):
//   0 pred_logits (BS,Q,NC) f32
//   1 pred_boxes  (BS,Q,4)  f32
//   2 tgt_bbox    (BS*T,4)  f32
//   3 ign_bbox    (BS*NI,4) f32
//   4 image_size_xyxy     (BS,4)   f32
//   5 image_size_xyxy_tgt (BS*T,4) f32
//   6 tgt_ids     (BS*T,)  i32
// Output: C_diag (BS,Q,T) followed by ioa_diag (BS,Q,NI), f32.

#define BSZ 16
#define QN  1000
#define NC  80
#define TN  100
#define NIN 8
#define QPB 10   // q rows per block

__global__ __launch_bounds__(128, 8)
void matcher_kernel(const float* __restrict__ logits,
                    const float* __restrict__ pboxes,
                    const float* __restrict__ tboxes,
                    const float* __restrict__ iboxes,
                    const float* __restrict__ img,
                    const float* __restrict__ img_tgt,
                    const int*   __restrict__ tids,
                    float* __restrict__ outC,
                    float* __restrict__ outIoa)
{
    const int b    = blockIdx.y;
    const int q0   = blockIdx.x * QPB;
    const int lane = threadIdx.x;   // 0..127: 0..99 targets, 100..107 ign

    // per-batch image normalization (reciprocals)
    const float* im = img + b * 4;
    const float iw0 = __frcp_rn(im[0]);
    const float ih0 = __frcp_rn(im[1]);
    const float iw1 = __frcp_rn(im[2]);
    const float ih1 = __frcp_rn(im[3]);

    // hoist per-target (or per-ign) data into registers
    float tx0 = 0.f, ty0 = 0.f, tx1 = 0.f, ty1 = 0.f;
    float tnx0 = 0.f, tny0 = 0.f, tnx1 = 0.f, tny1 = 0.f;
    float tarea = 0.f;
    int   cls = 0;

    if (lane < TN) {
        const int ti = b * TN + lane;
        const float4 tb = *reinterpret_cast<const float4*>(tboxes + ti * 4);
        tx0 = tb.x; ty0 = tb.y; tx1 = tb.z; ty1 = tb.w;
        const float4 it = *reinterpret_cast<const float4*>(img_tgt + ti * 4);
        tnx0 = tx0 * __frcp_rn(it.x);
        tny0 = ty0 * __frcp_rn(it.y);
        tnx1 = tx1 * __frcp_rn(it.z);
        tny1 = ty1 * __frcp_rn(it.w);
        tarea = (tx1 - tx0) * (ty1 - ty0);
        cls = tids[ti];
    } else if (lane < TN + NIN) {
        const int ii = b * NIN + (lane - TN);
        const float4 ib = *reinterpret_cast<const float4*>(iboxes + ii * 4);
        tx0 = ib.x; ty0 = ib.y; tx1 = ib.z; ty1 = ib.w;
    }

    const float* plog_base = logits + (size_t)(b * QN) * NC;
    const float* pbox_base = pboxes + (size_t)(b * QN) * 4;

    #pragma unroll 2
    for (int q = q0; q < q0 + QPB; ++q) {
        // broadcast pred box (same address across lanes -> 1 wavefront, L1 hit)
        const float4 pb = *reinterpret_cast<const float4*>(pbox_base + q * 4);
        const float px0 = pb.x, py0 = pb.y, px1 = pb.z, py1 = pb.w;
        const float parea = (px1 - px0) * (py1 - py0);

        if (lane < TN) {
            // ---- class cost ----
            const float x = __ldg(plog_base + q * NC + cls);
            const float p   = __frcp_rn(1.f + __expf(-x));
            const float omp = 1.f - p;
            const float pos = 0.25f * omp * omp * (-__logf(p + 1e-8f));
            const float neg = 0.75f * p * p * (-__logf(omp + 1e-8f));
            const float cclass = pos - neg;

            // ---- L1 bbox cost on normalized boxes ----
            const float cb = fabsf(px0 * iw0 - tnx0)
                           + fabsf(py0 * ih0 - tny0)
                           + fabsf(px1 * iw1 - tnx1)
                           + fabsf(py1 * ih1 - tny1);

            // ---- GIoU ----
            const float ixw = fminf(px1, tx1) - fmaxf(px0, tx0);
            const float iyw = fminf(py1, ty1) - fmaxf(py0, ty0);
            const float inter = fmaxf(ixw, 0.f) * fmaxf(iyw, 0.f);
            const float uni = parea + tarea - inter;
            const float exw = fmaxf(px1, tx1) - fminf(px0, tx0);
            const float eyw = fmaxf(py1, ty1) - fminf(py0, ty0);
            const float enc = fmaxf(exw, 0.f) * fmaxf(eyw, 0.f);
            // giou = inter/uni - (enc-uni)/enc = inter/uni + uni/enc - 1
            const float giou = __fdividef(inter, uni) + __fdividef(uni, enc) - 1.f;

            const float C = 5.f * cb + 2.f * cclass - 2.f * giou;
            outC[(size_t)((b * QN + q) * TN) + lane] = C;
        } else if (lane < TN + NIN) {
            // ---- intersection-over-area vs ignore boxes ----
            const float ixw = fminf(px1, tx1) - fmaxf(px0, tx0);
            const float iyw = fminf(py1, ty1) - fmaxf(py0, ty0);
            const float inter = fmaxf(ixw, 0.f) * fmaxf(iyw, 0.f);
            outIoa[(size_t)((b * QN + q) * NIN) + (lane - TN)] = __fdividef(inter, parea);
        }
    }
}

extern "C" void kernel_launch(void* const* d_in, const int* in_sizes, int n_in,
                              void* d_out, int out_size)
{
    const float* logits  = (const float*)d_in[0];
    const float* pboxes  = (const float*)d_in[1];
    const float* tboxes  = (const float*)d_in[2];
    const float* iboxes  = (const float*)d_in[3];
    const float* img     = (const float*)d_in[4];
    const float* img_tgt = (const float*)d_in[5];
    const int*   tids    = (const int*)d_in[6];

    float* outC   = (float*)d_out;
    float* outIoa = (float*)d_out + (size_t)BSZ * QN * TN;

    dim3 grid(QN / QPB, BSZ);
    matcher_kernel<<<grid, 128>>>(logits, pboxes, tboxes, iboxes,
                                  img, img_tgt, tids, outC, outIoa);
}

// round 3
// speedup vs baseline: 1.1231x; 1.1231x over previous
#include <cuda_runtime.h>
#include <cuda_bf16.h>

// HungarianMatcher cost computation, block-diagonal only.
// Shapes: BS=16, Q=1000, NC=80, T=100, NI=8
// Output: C_diag (BS,Q,T) followed by ioa_diag (BS,Q,NI), f32.

#define BSZ 16
#define QN  1000
#define NC  80
#define TN  100
#define NIN 8
#define QPB 10   // q rows per block

__global__ __launch_bounds__(128, 8)
void matcher_kernel(const float* __restrict__ logits,
                    const float* __restrict__ pboxes,
                    const float* __restrict__ tboxes,
                    const float* __restrict__ iboxes,
                    const float* __restrict__ img,
                    const float* __restrict__ img_tgt,
                    const int*   __restrict__ tids,
                    float* __restrict__ outC,
                    float* __restrict__ outIoa)
{
    const int b    = blockIdx.y;
    const int q0   = blockIdx.x * QPB;
    const int lane = threadIdx.x;   // 0..99 -> targets, 100..107 -> ign boxes

    // per-batch image normalization (reciprocals)
    const float* im = img + b * 4;
    const float iw0 = __frcp_rn(im[0]);
    const float ih0 = __frcp_rn(im[1]);
    const float iw1 = __frcp_rn(im[2]);
    const float ih1 = __frcp_rn(im[3]);

    // hoist per-target (or per-ign) data into registers
    float tx0 = 0.f, ty0 = 0.f, tx1 = 0.f, ty1 = 0.f;
    float tnx0 = 0.f, tny0 = 0.f, tnx1 = 0.f, tny1 = 0.f;
    float tarea = 0.f;
    int   cls = 0;

    const bool isC   = (lane < TN);
    const bool isIoa = (lane >= TN) && (lane < TN + NIN);

    if (isC) {
        const int ti = b * TN + lane;
        const float4 tb = *reinterpret_cast<const float4*>(tboxes + ti * 4);
        tx0 = tb.x; ty0 = tb.y; tx1 = tb.z; ty1 = tb.w;
        const float4 it = *reinterpret_cast<const float4*>(img_tgt + ti * 4);
        tnx0 = tx0 * __frcp_rn(it.x);
        tny0 = ty0 * __frcp_rn(it.y);
        tnx1 = tx1 * __frcp_rn(it.z);
        tny1 = ty1 * __frcp_rn(it.w);
        tarea = (tx1 - tx0) * (ty1 - ty0);
        cls = tids[ti];
    } else if (isIoa) {
        const int ii = b * NIN + (lane - TN);
        const float4 ib = *reinterpret_cast<const float4*>(iboxes + ii * 4);
        tx0 = ib.x; ty0 = ib.y; tx1 = ib.z; ty1 = ib.w;
    }

    const float* logit_lane = logits + (size_t)(b * QN + q0) * NC + cls;
    const float* pbox_base  = pboxes + (size_t)(b * QN) * 4;

    float* outC_lane   = outC   + (size_t)(b * QN + q0) * TN  + lane;
    float* outIoa_lane = outIoa + (size_t)(b * QN + q0) * NIN + (lane - TN);

    // software pipeline: prefetch iteration i+1's loads while computing i
    float4 pb_n = *reinterpret_cast<const float4*>(pbox_base + (q0) * 4);
    float  x_n  = isC ? __ldg(logit_lane) : 0.f;

    #pragma unroll
    for (int i = 0; i < QPB; ++i) {
        const float4 pb = pb_n;
        const float  x  = x_n;
        if (i + 1 < QPB) {
            pb_n = *reinterpret_cast<const float4*>(pbox_base + (q0 + i + 1) * 4);
            x_n  = isC ? __ldg(logit_lane + (i + 1) * NC) : 0.f;
        }

        const float px0 = pb.x, py0 = pb.y, px1 = pb.z, py1 = pb.w;
        const float parea = (px1 - px0) * (py1 - py0);

        if (isC) {
            // ---- focal class cost with a single log ----
            // e = exp(-x); p = 1/(1+e); -log(p) = log(1+e) = L; -log(1-p) = x + L
            const float e   = __expf(-x);
            const float s   = 1.f + e;
            const float p   = __frcp_rn(s);   // independent of L: short chain
            const float L   = __logf(s);
            const float omp = 1.f - p;
            const float pos = 0.25f * omp * omp * L;
            const float neg = 0.75f * p * p * (x + L);
            const float cclass = pos - neg;

            // ---- L1 bbox cost on normalized boxes ----
            const float cb = fabsf(px0 * iw0 - tnx0)
                           + fabsf(py0 * ih0 - tny0)
                           + fabsf(px1 * iw1 - tnx1)
                           + fabsf(py1 * ih1 - tny1);

            // ---- GIoU with a single reciprocal ----
            const float ixw = fminf(px1, tx1) - fmaxf(px0, tx0);
            const float iyw = fminf(py1, ty1) - fmaxf(py0, ty0);
            const float inter = fmaxf(ixw, 0.f) * fmaxf(iyw, 0.f);
            const float uni = parea + tarea - inter;
            const float exw = fmaxf(px1, tx1) - fminf(px0, tx0);
            const float eyw = fmaxf(py1, ty1) - fminf(py0, ty0);
            const float enc = fmaxf(exw, 0.f) * fmaxf(eyw, 0.f);
            // giou = inter/uni + uni/enc - 1 = (inter*enc + uni*uni) / (uni*enc) - 1
            const float r    = __frcp_rn(uni * enc);
            const float giou = fmaf(inter * enc + uni * uni, r, -1.f);

            const float C = fmaf(5.f, cb, fmaf(2.f, cclass, -2.f * giou));
            outC_lane[i * TN] = C;
        } else if (isIoa) {
            const float ixw = fminf(px1, tx1) - fmaxf(px0, tx0);
            const float iyw = fminf(py1, ty1) - fmaxf(py0, ty0);
            const float inter = fmaxf(ixw, 0.f) * fmaxf(iyw, 0.f);
            outIoa_lane[i * NIN] = inter * __frcp_rn(parea);
        }
    }
}

extern "C" void kernel_launch(void* const* d_in, const int* in_sizes, int n_in,
                              void* d_out, int out_size)
{
    const float* logits  = (const float*)d_in[0];
    const float* pboxes  = (const float*)d_in[1];
    const float* tboxes  = (const float*)d_in[2];
    const float* iboxes  = (const float*)d_in[3];
    const float* img     = (const float*)d_in[4];
    const float* img_tgt = (const float*)d_in[5];
    const int*   tids    = (const int*)d_in[6];

    float* outC   = (float*)d_out;
    float* outIoa = (float*)d_out + (size_t)BSZ * QN * TN;

    dim3 grid(QN / QPB, BSZ);
    matcher_kernel<<<grid, 128>>>(logits, pboxes, tboxes, iboxes,
                                  img, img_tgt, tids, outC, outIoa);
}